// round 11
// baseline (speedup 1.0000x reference)
#include <cuda_runtime.h>

// ASTGC_37976100831379 — R6
//
// Dead-graph analysis (verified R1, rel_err=0.0 bitwise): the reference
// returns fusion_out[:, 0], the star-graph hub node, which receives no
// messages (its concat row is an explicit zeros tensor). So
//
//     out[b, s, 0] = fgcn_b[s]      b in [0,32), s in [0,48)
//
// -> 48-float broadcast into [32,48] (6 KB). All throughput metrics ~0%;
// time = launch ramp + CTA dispatch + cold-miss + drain. Measured curve:
// grid 1->4->6->8 gave kernel 4.38->4.26->3.65->3.52 us (monotone with
// overlap width). R6 probes grid=16: 16 CTAs on 16 distinct SMs, each a
// single warp (24 threads: 12 float4 cols x 2 rows), one LDG.128 + one
// STG.128 per thread, zero arithmetic on the load path.

#define ASTGC_S 48

__global__ void __launch_bounds__(24, 1)
astgc_bias_broadcast_r6(const float4* __restrict__ bias4,
                        float4* __restrict__ out4) {
    unsigned tx  = threadIdx.x;                            // 0..11 (float4 col)
    unsigned row = blockIdx.x * blockDim.y + threadIdx.y;  // 0..31 (batch)
    out4[row * 12u + tx] = bias4[tx];
}

extern "C" void kernel_launch(void* const* d_in, const int* in_sizes, int n_in,
                              void* d_out, int out_size) {
    // Locate fgcn_b: the unique input with exactly S=48 elements.
    int bias_idx = -1;
    for (int i = 0; i < n_in; ++i) {
        if (in_sizes[i] == ASTGC_S) { bias_idx = i; break; }
    }
    if (bias_idx < 0) bias_idx = 30;  // setup_inputs order fallback

    const float4* bias4 = (const float4*)d_in[bias_idx];
    float4* out4 = (float4*)d_out;

    dim3 block(12, 2);   // 24 threads = 1 warp (partially filled)
    dim3 grid(16);       // 16 * 2 = 32 batch rows
    astgc_bias_broadcast_r6<<<grid, block>>>(bias4, out4);
}